// round 11
// baseline (speedup 1.0000x reference)
#include <cuda_runtime.h>

#define D_DIM 256
#define NCLS 100
#define K1_CTAS 64
#define K1_THREADS 512
#define GSIZE (NCLS * D_DIM)      // 25600 floats = 100 KB
#define K2_THREADS 1024
#define NP4 (D_DIM / 4)           // 64 float4 per class row
#define PGRP 16                   // p-groups in K2
#define PPER (K1_CTAS / PGRP)     // 4 partials per thread

// Scratch (__device__ globals; allocation forbidden). Fully overwritten each
// launch; ticket reset by finishing CTA -> graph-replay deterministic.
__device__ __align__(16) float g_part[(size_t)K1_CTAS * GSIZE];
__device__ __align__(16) float s_part[(size_t)K1_CTAS * D_DIM];
__device__ float t_part[K1_CTAS];
__device__ double sumsq_cls[NCLS];
__device__ unsigned int g_counter = 0;

// ---------------------------------------------------------------------------
// K1: 64 CTAs x 512 threads. Column col = tid&255 (coalesced LDG.32); half
// h = tid>>8 owns a private 100KB smem copy (conflict-free column ownership).
// ---------------------------------------------------------------------------
__global__ void __launch_bounds__(K1_THREADS)
k_accum(const float* __restrict__ feat,
        const void* __restrict__ label_raw, int B) {
    extern __shared__ float sG[];          // [2 * GSIZE]
    __shared__ float sS[K1_THREADS];
    __shared__ float red[K1_THREADS / 32];
    __shared__ int s_is64;

    const int tid = threadIdx.x;
    const int col = tid & 255;
    const int h   = tid >> 8;
    const int cta = blockIdx.x;

    // vectorized smem zero (STS.128)
    {
        float4* z = (float4*)sG;
        #pragma unroll 5
        for (int i = tid; i < 2 * GSIZE / 4; i += K1_THREADS)
            z[i] = make_float4(0.f, 0.f, 0.f, 0.f);
    }

    // parallel label-dtype sniff: 16 lanes, ONE load latency (was 16 serial).
    // int32 labels in [0,100) masquerading as int64 words fail the <100 test
    // with overwhelming probability.
    if (tid < 32) {
        const unsigned long long* p = (const unsigned long long*)label_raw;
        int n = (B < 16) ? B : 16;
        int bad = (tid < n) && (p[tid] >= 100ULL);
        unsigned m = __ballot_sync(0xFFFFFFFFu, bad);
        if (tid == 0) s_is64 = (m == 0u);
    }
    __syncthreads();
    const int is64 = s_is64;

    float* myG = sG + h * GSIZE;

    const int rows = (B + K1_CTAS - 1) / K1_CTAS;
    const int base = cta * rows;
    const int end  = (base + rows < B) ? (base + rows) : B;
    const int hr   = (rows + 1) >> 1;
    const int r0   = base + h * hr;
    int r1 = r0 + hr; if (r1 > end) r1 = end;

    float t = 0.0f, s = 0.0f;

    if (is64) {
        const long long* lab = (const long long*)label_raw;
        int r = r0;
        for (; r + 4 <= r1; r += 4) {
            float v0 = feat[(size_t)(r + 0) * D_DIM + col];
            float v1 = feat[(size_t)(r + 1) * D_DIM + col];
            float v2 = feat[(size_t)(r + 2) * D_DIM + col];
            float v3 = feat[(size_t)(r + 3) * D_DIM + col];
            int l0 = (int)lab[r + 0], l1 = (int)lab[r + 1];
            int l2 = (int)lab[r + 2], l3 = (int)lab[r + 3];
            t = fmaf(v0, v0, t);  s += v0;  myG[l0 * D_DIM + col] += v0;
            t = fmaf(v1, v1, t);  s += v1;  myG[l1 * D_DIM + col] += v1;
            t = fmaf(v2, v2, t);  s += v2;  myG[l2 * D_DIM + col] += v2;
            t = fmaf(v3, v3, t);  s += v3;  myG[l3 * D_DIM + col] += v3;
        }
        for (; r < r1; ++r) {
            float v = feat[(size_t)r * D_DIM + col];
            int l = (int)lab[r];
            t = fmaf(v, v, t);  s += v;  myG[l * D_DIM + col] += v;
        }
    } else {
        const int* lab = (const int*)label_raw;
        int r = r0;
        for (; r + 4 <= r1; r += 4) {
            float v0 = feat[(size_t)(r + 0) * D_DIM + col];
            float v1 = feat[(size_t)(r + 1) * D_DIM + col];
            float v2 = feat[(size_t)(r + 2) * D_DIM + col];
            float v3 = feat[(size_t)(r + 3) * D_DIM + col];
            int l0 = lab[r + 0], l1 = lab[r + 1];
            int l2 = lab[r + 2], l3 = lab[r + 3];
            t = fmaf(v0, v0, t);  s += v0;  myG[l0 * D_DIM + col] += v0;
            t = fmaf(v1, v1, t);  s += v1;  myG[l1 * D_DIM + col] += v1;
            t = fmaf(v2, v2, t);  s += v2;  myG[l2 * D_DIM + col] += v2;
            t = fmaf(v3, v3, t);  s += v3;  myG[l3 * D_DIM + col] += v3;
        }
        for (; r < r1; ++r) {
            float v = feat[(size_t)r * D_DIM + col];
            int l = lab[r];
            t = fmaf(v, v, t);  s += v;  myG[l * D_DIM + col] += v;
        }
    }
    sS[tid] = s;
    __syncthreads();

    // merge the two copies, write per-CTA partial (LDS.128 + STG.128)
    {
        const float4* a = (const float4*)sG;
        const float4* b = (const float4*)(sG + GSIZE);
        float4* gp4 = (float4*)(g_part + (size_t)cta * GSIZE);
        #pragma unroll 4
        for (int i = tid; i < GSIZE / 4; i += K1_THREADS) {
            float4 x = a[i], y = b[i];
            gp4[i] = make_float4(x.x + y.x, x.y + y.y, x.z + y.z, x.w + y.w);
        }
    }
    if (h == 0)
        s_part[(size_t)cta * D_DIM + col] = sS[col] + sS[col + 256];

    // block-reduce t (fixed order -> deterministic)
    #pragma unroll
    for (int o = 16; o > 0; o >>= 1) t += __shfl_down_sync(0xFFFFFFFFu, t, o);
    if ((tid & 31) == 0) red[tid >> 5] = t;
    __syncthreads();
    if (tid == 0) {
        float v = 0.0f;
        #pragma unroll
        for (int w = 0; w < K1_THREADS / 32; ++w) v += red[w];
        t_part[cta] = v;
    }
}

// ---------------------------------------------------------------------------
// K2: 100 CTAs x 1024 threads, float4 loads. Thread t: d4 = t&63, pg = t>>6
// reduces 4 partials with LDG.128 (stride GSIZE); 16-way smem combine; fp64
// square reduce -> sumsq_cls[c]. Last CTA (ticket) computes final fp64 sum.
// __launch_bounds__(1024) caps regs at 64/thread so the launch always fits.
// ---------------------------------------------------------------------------
__global__ void __launch_bounds__(K2_THREADS)
k_reduce_final(float* __restrict__ out) {
    __shared__ float4 sv[PGRP][NP4];   // 16 KB
    __shared__ double redd[32];
    __shared__ int s_last;

    const int c  = blockIdx.x;
    const int t  = threadIdx.x;
    const int d4 = t & (NP4 - 1);
    const int pg = t >> 6;             // 0..15

    {
        const float4* bp = (const float4*)(g_part + (size_t)(pg * PPER) * GSIZE
                                           + (size_t)c * D_DIM) + d4;
        const int st = GSIZE / 4;      // float4 stride between partials
        float4 a0 = bp[0], a1 = bp[st], a2 = bp[2 * st], a3 = bp[3 * st];
        sv[pg][d4] = make_float4(a0.x + a1.x + a2.x + a3.x,
                                 a0.y + a1.y + a2.y + a3.y,
                                 a0.z + a1.z + a2.z + a3.z,
                                 a0.w + a1.w + a2.w + a3.w);
    }
    __syncthreads();

    if (t < NP4) {
        float4 g = sv[0][t];
        #pragma unroll
        for (int p = 1; p < PGRP; ++p) {
            float4 v = sv[p][t];
            g.x += v.x; g.y += v.y; g.z += v.z; g.w += v.w;
        }
        double sq = (double)g.x * g.x + (double)g.y * g.y
                  + (double)g.z * g.z + (double)g.w * g.w;
        #pragma unroll
        for (int o = 16; o > 0; o >>= 1) sq += __shfl_down_sync(0xFFFFFFFFu, sq, o);
        if ((t & 31) == 0) redd[t >> 5] = sq;
    }
    __syncthreads();
    if (t == 0) {
        sumsq_cls[c] = redd[0] + redd[1];
        __threadfence();
        unsigned int old = atomicAdd(&g_counter, 1u);
        s_last = (old == (unsigned int)(gridDim.x - 1)) ? 1 : 0;
    }
    __syncthreads();
    if (!s_last) return;
    __threadfence();

    // ---- final combination (last CTA) ----
    {
        const float4* bp = (const float4*)(s_part + (size_t)(pg * PPER) * D_DIM) + d4;
        const int st = D_DIM / 4;
        float4 a0 = bp[0], a1 = bp[st], a2 = bp[2 * st], a3 = bp[3 * st];
        sv[pg][d4] = make_float4(a0.x + a1.x + a2.x + a3.x,
                                 a0.y + a1.y + a2.y + a3.y,
                                 a0.z + a1.z + a2.z + a3.z,
                                 a0.w + a1.w + a2.w + a3.w);
    }
    __syncthreads();

    double val = 0.0;
    if (t < NP4) {
        float4 sA = sv[0][t];
        #pragma unroll
        for (int p = 1; p < PGRP; ++p) {
            float4 v = sv[p][t];
            sA.x += v.x; sA.y += v.y; sA.z += v.z; sA.w += v.w;
        }
        val = 0.5 * ((double)sA.x * sA.x + (double)sA.y * sA.y
                   + (double)sA.z * sA.z + (double)sA.w * sA.w);
        val += (double)t_part[t];      // t < 64 == K1_CTAS
    }
    if (t < NCLS) val -= 1.5 * sumsq_cls[t];

    #pragma unroll
    for (int o = 16; o > 0; o >>= 1) val += __shfl_down_sync(0xFFFFFFFFu, val, o);
    if ((t & 31) == 0) redd[t >> 5] = val;
    __syncthreads();
    if (t == 0) {
        double v = 0.0;
        #pragma unroll
        for (int w = 0; w < K2_THREADS / 32; ++w) v += redd[w];
        out[0] = (float)v;
        g_counter = 0;   // reset for next graph replay
    }
}

// ---------------------------------------------------------------------------
extern "C" void kernel_launch(void* const* d_in, const int* in_sizes, int n_in,
                              void* d_out, int out_size) {
    const float* feat = (const float*)d_in[0];
    const void* label = d_in[1];
    const int B = in_sizes[1];

    cudaFuncSetAttribute(k_accum, cudaFuncAttributeMaxDynamicSharedMemorySize,
                         2 * GSIZE * (int)sizeof(float));

    k_accum<<<K1_CTAS, K1_THREADS, 2 * GSIZE * sizeof(float)>>>(feat, label, B);
    k_reduce_final<<<NCLS, K2_THREADS>>>((float*)d_out);
}

// round 13
// speedup vs baseline: 1.0122x; 1.0122x over previous
#include <cuda_runtime.h>

#define D_DIM 256
#define NCLS 100
#define K1_CTAS 64
#define K1_THREADS 512
#define GSIZE (NCLS * D_DIM)      // 25600 floats = 100 KB

#define K2_THREADS 1024
#define K2_CTAS (NCLS * 2)        // (class, d-half)
#define HALF 128                  // columns per K2 CTA
#define PG2 8                     // p-groups
#define PPER2 (K1_CTAS / PG2)     // 8 partials per thread

// Scratch (__device__ globals; allocation forbidden). Fully overwritten each
// launch; sumsq_cls zeroed by K1; ticket reset by finishing CTA.
__device__ __align__(16) float g_part[(size_t)K1_CTAS * GSIZE];
__device__ __align__(16) float s_part[(size_t)K1_CTAS * D_DIM];
__device__ float t_part[K1_CTAS];
__device__ double sumsq_cls[NCLS];
__device__ unsigned int g_counter = 0;

// ---------------------------------------------------------------------------
// K1: 64 CTAs x 512 threads. Column col = tid&255 (coalesced LDG.32); half
// h = tid>>8 owns a private 100KB smem copy (conflict-free column ownership).
// ---------------------------------------------------------------------------
__global__ void __launch_bounds__(K1_THREADS)
k_accum(const float* __restrict__ feat,
        const void* __restrict__ label_raw, int B) {
    extern __shared__ float sG[];          // [2 * GSIZE]
    __shared__ float sS[K1_THREADS];
    __shared__ float red[K1_THREADS / 32];
    __shared__ int s_is64;

    const int tid = threadIdx.x;
    const int col = tid & 255;
    const int h   = tid >> 8;
    const int cta = blockIdx.x;

    // zero sumsq_cls for this launch (stream-ordered before K2's atomics)
    if (cta == 0 && tid < NCLS) sumsq_cls[tid] = 0.0;

    // vectorized smem zero (STS.128)
    {
        float4* z = (float4*)sG;
        #pragma unroll 5
        for (int i = tid; i < 2 * GSIZE / 4; i += K1_THREADS)
            z[i] = make_float4(0.f, 0.f, 0.f, 0.f);
    }

    // parallel label-dtype sniff (int64 vs silently-downgraded int32)
    if (tid < 32) {
        const unsigned long long* p = (const unsigned long long*)label_raw;
        int n = (B < 16) ? B : 16;
        int bad = (tid < n) && (p[tid] >= 100ULL);
        unsigned m = __ballot_sync(0xFFFFFFFFu, bad);
        if (tid == 0) s_is64 = (m == 0u);
    }
    __syncthreads();
    const int is64 = s_is64;

    float* myG = sG + h * GSIZE;

    const int rows = (B + K1_CTAS - 1) / K1_CTAS;
    const int base = cta * rows;
    const int end  = (base + rows < B) ? (base + rows) : B;
    const int hr   = (rows + 1) >> 1;
    const int r0   = base + h * hr;
    int r1 = r0 + hr; if (r1 > end) r1 = end;

    float t = 0.0f, s = 0.0f;

    if (is64) {
        const long long* lab = (const long long*)label_raw;
        int r = r0;
        for (; r + 4 <= r1; r += 4) {
            float v0 = feat[(size_t)(r + 0) * D_DIM + col];
            float v1 = feat[(size_t)(r + 1) * D_DIM + col];
            float v2 = feat[(size_t)(r + 2) * D_DIM + col];
            float v3 = feat[(size_t)(r + 3) * D_DIM + col];
            int l0 = (int)lab[r + 0], l1 = (int)lab[r + 1];
            int l2 = (int)lab[r + 2], l3 = (int)lab[r + 3];
            t = fmaf(v0, v0, t);  s += v0;  myG[l0 * D_DIM + col] += v0;
            t = fmaf(v1, v1, t);  s += v1;  myG[l1 * D_DIM + col] += v1;
            t = fmaf(v2, v2, t);  s += v2;  myG[l2 * D_DIM + col] += v2;
            t = fmaf(v3, v3, t);  s += v3;  myG[l3 * D_DIM + col] += v3;
        }
        for (; r < r1; ++r) {
            float v = feat[(size_t)r * D_DIM + col];
            int l = (int)lab[r];
            t = fmaf(v, v, t);  s += v;  myG[l * D_DIM + col] += v;
        }
    } else {
        const int* lab = (const int*)label_raw;
        int r = r0;
        for (; r + 4 <= r1; r += 4) {
            float v0 = feat[(size_t)(r + 0) * D_DIM + col];
            float v1 = feat[(size_t)(r + 1) * D_DIM + col];
            float v2 = feat[(size_t)(r + 2) * D_DIM + col];
            float v3 = feat[(size_t)(r + 3) * D_DIM + col];
            int l0 = lab[r + 0], l1 = lab[r + 1];
            int l2 = lab[r + 2], l3 = lab[r + 3];
            t = fmaf(v0, v0, t);  s += v0;  myG[l0 * D_DIM + col] += v0;
            t = fmaf(v1, v1, t);  s += v1;  myG[l1 * D_DIM + col] += v1;
            t = fmaf(v2, v2, t);  s += v2;  myG[l2 * D_DIM + col] += v2;
            t = fmaf(v3, v3, t);  s += v3;  myG[l3 * D_DIM + col] += v3;
        }
        for (; r < r1; ++r) {
            float v = feat[(size_t)r * D_DIM + col];
            int l = lab[r];
            t = fmaf(v, v, t);  s += v;  myG[l * D_DIM + col] += v;
        }
    }
    sS[tid] = s;
    __syncthreads();

    // merge the two copies, write per-CTA partial (LDS.128 + STG.128)
    {
        const float4* a = (const float4*)sG;
        const float4* b = (const float4*)(sG + GSIZE);
        float4* gp4 = (float4*)(g_part + (size_t)cta * GSIZE);
        #pragma unroll 4
        for (int i = tid; i < GSIZE / 4; i += K1_THREADS) {
            float4 x = a[i], y = b[i];
            gp4[i] = make_float4(x.x + y.x, x.y + y.y, x.z + y.z, x.w + y.w);
        }
    }
    if (h == 0)
        s_part[(size_t)cta * D_DIM + col] = sS[col] + sS[col + 256];

    // block-reduce t (fixed order -> deterministic)
    #pragma unroll
    for (int o = 16; o > 0; o >>= 1) t += __shfl_down_sync(0xFFFFFFFFu, t, o);
    if ((tid & 31) == 0) red[tid >> 5] = t;
    __syncthreads();
    if (tid == 0) {
        float v = 0.0f;
        #pragma unroll
        for (int w = 0; w < K1_THREADS / 32; ++w) v += red[w];
        t_part[cta] = v;
    }
}

// ---------------------------------------------------------------------------
// K2: 200 CTAs x 1024 threads (class c = bx>>1, d-half e = bx&1). Thread:
// dl = t&127, pg = t>>7 reduces 8 scalar partials (independent LDG.32);
// 8-way smem combine; fp64 half-sumsq atomicAdd into sumsq_cls[c] (exactly
// two adds per class -> order-independent, deterministic). Last CTA (ticket)
// computes the final fp64 combination.
// ---------------------------------------------------------------------------
__global__ void __launch_bounds__(K2_THREADS)
k_reduce_final(float* __restrict__ out) {
    __shared__ float svf[PG2 * HALF];      // 4 KB, reused by the tail
    __shared__ double redd[K2_THREADS / 32];
    __shared__ int s_last;

    const int bx = blockIdx.x;
    const int c  = bx >> 1;
    const int e  = bx & 1;
    const int t  = threadIdx.x;
    const int dl = t & (HALF - 1);
    const int pg = t >> 7;                 // 0..7

    {
        const float* bp = g_part + (size_t)(pg * PPER2) * GSIZE
                        + (size_t)c * D_DIM + e * HALF + dl;
        float g = 0.0f;
        #pragma unroll
        for (int p = 0; p < PPER2; ++p) g += bp[(size_t)p * GSIZE];
        svf[pg * HALF + dl] = g;
    }
    __syncthreads();

    if (t < HALF) {
        float g = svf[t];
        #pragma unroll
        for (int p = 1; p < PG2; ++p) g += svf[p * HALF + t];
        double sq = (double)g * (double)g;
        #pragma unroll
        for (int o = 16; o > 0; o >>= 1) sq += __shfl_down_sync(0xFFFFFFFFu, sq, o);
        if ((t & 31) == 0) redd[t >> 5] = sq;
    }
    __syncthreads();
    if (t == 0) {
        double v = redd[0] + redd[1] + redd[2] + redd[3];
        atomicAdd(&sumsq_cls[c], v);       // 2 adds/class: order-independent
        __threadfence();
        unsigned int old = atomicAdd(&g_counter, 1u);
        s_last = (old == (unsigned int)(gridDim.x - 1)) ? 1 : 0;
    }
    __syncthreads();
    if (!s_last) return;
    __threadfence();

    // ---- final combination (last CTA, 1024 threads) ----
    {
        const int d  = t & 255;
        const int pq = t >> 8;             // 0..3, 16 partials each
        const float* bp = s_part + (size_t)(pq * 16) * D_DIM + d;
        float s = 0.0f;
        #pragma unroll
        for (int p = 0; p < 16; ++p) s += bp[(size_t)p * D_DIM];
        svf[pq * D_DIM + d] = s;           // 4*256 = 1024 floats = 4 KB ✓
    }
    __syncthreads();

    double val = 0.0;
    if (t < D_DIM) {
        float s = svf[t] + svf[D_DIM + t] + svf[2 * D_DIM + t] + svf[3 * D_DIM + t];
        val = 0.5 * (double)s * (double)s;
        if (t < K1_CTAS) val += (double)t_part[t];
    }
    if (t < NCLS) val -= 1.5 * sumsq_cls[t];

    #pragma unroll
    for (int o = 16; o > 0; o >>= 1) val += __shfl_down_sync(0xFFFFFFFFu, val, o);
    if ((t & 31) == 0) redd[t >> 5] = val;
    __syncthreads();
    if (t == 0) {
        double v = 0.0;
        #pragma unroll
        for (int w = 0; w < K2_THREADS / 32; ++w) v += redd[w];
        out[0] = (float)v;
        g_counter = 0;   // reset for next graph replay
    }
}

// ---------------------------------------------------------------------------
extern "C" void kernel_launch(void* const* d_in, const int* in_sizes, int n_in,
                              void* d_out, int out_size) {
    const float* feat = (const float*)d_in[0];
    const void* label = d_in[1];
    const int B = in_sizes[1];

    cudaFuncSetAttribute(k_accum, cudaFuncAttributeMaxDynamicSharedMemorySize,
                         2 * GSIZE * (int)sizeof(float));

    k_accum<<<K1_CTAS, K1_THREADS, 2 * GSIZE * sizeof(float)>>>(feat, label, B);
    k_reduce_final<<<K2_CTAS, K2_THREADS>>>((float*)d_out);
}